// round 6
// baseline (speedup 1.0000x reference)
#include <cuda_runtime.h>
#include <math.h>
#include <stddef.h>

#define RS 507904          /* 992 * 512 */
#define NT 512

__device__ float g_W0[1024];
__device__ float g_PE[16384];
__device__ float g_GCS[4096];
__device__ float g_Y[524288];
__device__ float g_K[RS];
__device__ float g_V[RS];
__device__ float g_XB[RS];
__device__ float g_LOG[320000];
__device__ unsigned g_count;
__device__ volatile unsigned g_sense;

// ------------------------------ grid barrier -------------------------------
__device__ __forceinline__ void gsync()
{
    __threadfence();
    __syncthreads();
    if (threadIdx.x == 0) {
        unsigned gen = g_sense;
        if (atomicAdd(&g_count, 1u) == gridDim.x - 1) {
            g_count = 0;
            __threadfence();
            g_sense = gen + 1;
        } else {
            while (g_sense == gen) __nanosleep(32);
        }
    }
    __syncthreads();
    __threadfence();
}

// ------------------------------ cp.async -----------------------------------
__device__ __forceinline__ void cpa16(float* s, const float* g)
{
    unsigned sa = (unsigned)__cvta_generic_to_shared(s);
    asm volatile("cp.async.cg.shared.global [%0], [%1], 16;\n" :: "r"(sa), "l"(g));
}
#define CPCOMMIT() asm volatile("cp.async.commit_group;\n" ::: "memory")
#define CPWAIT1()  asm volatile("cp.async.wait_group 1;\n" ::: "memory")

// fill one 8x512 weight chunk (4096 floats) : 2 float4 per thread
__device__ __forceinline__ void fill8(float* buf, const float* gp)
{
    int tid = threadIdx.x;
#pragma unroll
    for (int it = 0; it < 2; ++it) {
        int slot = it * NT + tid;              // float4 slot 0..1023
        cpa16(buf + slot * 4, gp + slot * 4);
    }
}

// ---------------- GEMM: 4 rows x 512 cols, K=512, acc[4]/thread ------------
// thread: row = tid>>7 (0..3), cg = tid&127 (4 cols at cg*4)
__device__ __forceinline__ void gemm4(const float* __restrict__ Wp,
                                      const float* __restrict__ ins,
                                      float* __restrict__ Ws, float acc[4])
{
    int tid = threadIdx.x;
    int row = tid >> 7, cg = tid & 127;
    fill8(Ws, Wp); CPCOMMIT();
    for (int c = 0; c < 64; ++c) {
        float* curb = Ws + (c & 1) * 4096;
        float* nxtb = Ws + ((c & 1) ^ 1) * 4096;
        if (c < 63) fill8(nxtb, Wp + (size_t)(c + 1) * 4096);
        CPCOMMIT();
        CPWAIT1();
        __syncthreads();
        const float* ap = ins + row * 512 + c * 8;
        float4 a0 = ((const float4*)ap)[0];
        float4 a1 = ((const float4*)ap)[1];
        float av[8] = {a0.x, a0.y, a0.z, a0.w, a1.x, a1.y, a1.z, a1.w};
#pragma unroll
        for (int kk = 0; kk < 8; ++kk) {
            float4 w4 = ((const float4*)(curb + kk * 512))[cg];
            acc[0] += av[kk] * w4.x;
            acc[1] += av[kk] * w4.y;
            acc[2] += av[kk] * w4.z;
            acc[3] += av[kk] * w4.w;
        }
        __syncthreads();
    }
}

// epilogue: acc + bias (opt relu) -> dst rows (stride 512, smem or gmem)
__device__ __forceinline__ void epi4(const float acc[4], const float* __restrict__ bias,
                                     float* __restrict__ dst, int relu)
{
    int tid = threadIdx.x, row = tid >> 7, cg = tid & 127;
    float4 bb = ((const float4*)bias)[cg];
    float4 o = make_float4(acc[0] + bb.x, acc[1] + bb.y, acc[2] + bb.z, acc[3] + bb.w);
    if (relu) {
        o.x = fmaxf(o.x, 0.f); o.y = fmaxf(o.y, 0.f);
        o.z = fmaxf(o.z, 0.f); o.w = fmaxf(o.w, 0.f);
    }
    ((float4*)(dst + row * 512))[cg] = o;
    __syncthreads();
}

// load 4 input rows (r0..r0+3) into Xs; fromY -> strided (b,s) layout
__device__ __forceinline__ void loadX(const float* __restrict__ src, int fromY,
                                      int cur, int r0, float* __restrict__ Xs)
{
    int slot = threadIdx.x;                    // 512 float4 slots
    int row = slot >> 7, c4 = slot & 127;
    int gr = r0 + row;
    const float* rp;
    if (fromY) { int b = gr / cur, s2 = gr - b * cur; rp = src + b * 16384 + s2 * 512; }
    else        rp = src + (size_t)gr * 512;
    ((float4*)Xs)[slot] = ((const float4*)rp)[c4];
    __syncthreads();
}

// LayerNorm of (a + res) over 512, 4 rows, 128 thr/row -> dst rows stride 512
__device__ __forceinline__ void ln4(const float* __restrict__ a, const float* __restrict__ res,
                                    const float* __restrict__ gg, const float* __restrict__ bb,
                                    float* __restrict__ dst)
{
    __shared__ float red[16];
    int tid = threadIdx.x, row = tid >> 7, cg = tid & 127, wid = tid >> 5, l = tid & 31;
    float4 va = ((const float4*)(a + row * 512))[cg];
    float4 vr = ((const float4*)(res + row * 512))[cg];
    float x0 = va.x + vr.x, x1 = va.y + vr.y, x2 = va.z + vr.z, x3 = va.w + vr.w;
    float s = x0 + x1 + x2 + x3;
#pragma unroll
    for (int o = 16; o; o >>= 1) s += __shfl_xor_sync(0xffffffffu, s, o);
    if (l == 0) red[wid] = s;
    __syncthreads();
    float mean = (red[row*4] + red[row*4+1] + red[row*4+2] + red[row*4+3]) * (1.f/512.f);
    float d0 = x0 - mean, d1 = x1 - mean, d2 = x2 - mean, d3 = x3 - mean;
    float vs = d0*d0 + d1*d1 + d2*d2 + d3*d3;
#pragma unroll
    for (int o = 16; o; o >>= 1) vs += __shfl_xor_sync(0xffffffffu, vs, o);
    __syncthreads();
    if (l == 0) red[wid] = vs;
    __syncthreads();
    float inv = rsqrtf((red[row*4] + red[row*4+1] + red[row*4+2] + red[row*4+3]) * (1.f/512.f) + 1e-5f);
    float4 gv = ((const float4*)gg)[cg];
    float4 bv = ((const float4*)bb)[cg];
    float4 o4 = make_float4(gv.x*d0*inv + bv.x, gv.y*d1*inv + bv.y,
                            gv.z*d2*inv + bv.z, gv.w*d3*inv + bv.w);
    ((float4*)(dst + row * 512))[cg] = o4;
    __syncthreads();
}

// self-attention for 4 rows (Q in Cs) -> Ds; K,V from gmem
__device__ __forceinline__ void attn4(const float* __restrict__ Cs, float* __restrict__ Ds,
                                      int r0, int cur)
{
    int wid = threadIdx.x >> 5, l = threadIdx.x & 31;
#pragma unroll
    for (int u = wid; u < 32; u += 16) {
        int rl = u >> 3, h = u & 7;
        int gr = r0 + rl, b = gr / cur;
        const float* qrow = Cs + rl * 512 + h * 64;
        float q0 = qrow[l], q1 = qrow[l + 32];
        const float* Kb = g_K + (size_t)(b * cur) * 512 + h * 64;
        const float* Vb = g_V + (size_t)(b * cur) * 512 + h * 64;
        float my = -3.0e38f;
        for (int j = 0; j < cur; ++j) {
            float s = q0 * Kb[(size_t)j * 512 + l] + q1 * Kb[(size_t)j * 512 + l + 32];
#pragma unroll
            for (int o = 16; o; o >>= 1) s += __shfl_xor_sync(0xffffffffu, s, o);
            if (l == j) my = s * 0.125f;
        }
        float mx = (l < cur) ? my : -3.0e38f;
#pragma unroll
        for (int o = 16; o; o >>= 1) mx = fmaxf(mx, __shfl_xor_sync(0xffffffffu, mx, o));
        float p = (l < cur) ? expf(my - mx) : 0.f;
        float sum = p;
#pragma unroll
        for (int o = 16; o; o >>= 1) sum += __shfl_xor_sync(0xffffffffu, sum, o);
        p /= sum;
        float a0 = 0.f, a1 = 0.f;
        for (int j = 0; j < cur; ++j) {
            float pj = __shfl_sync(0xffffffffu, p, j);
            a0 += pj * Vb[(size_t)j * 512 + l];
            a1 += pj * Vb[(size_t)j * 512 + l + 32];
        }
        float* dp = Ds + rl * 512 + h * 64;
        dp[l] = a0; dp[l + 32] = a1;
    }
    __syncthreads();
}

// collapsed cross-attention, in place on Cs (4 rows); warps 0-3
__device__ __forceinline__ void cross4(float* __restrict__ Cs, int r0, int cur,
                                       int n, const float* __restrict__ bca)
{
    int wid = threadIdx.x >> 5, l = threadIdx.x & 31;
    if (wid < 4) {
        int gr = r0 + wid, b = gr / cur;
        float wl = (l < cur) ? g_W0[b * 32 + l] : 0.f;
        const float* csk = g_GCS + (n * 2 + 0) * 512;
        const float* csv = g_GCS + (n * 2 + 1) * 512;
        const float* bv  = bca + (size_t)(n * 4 + 2) * 512;
        float dh[8];
#pragma unroll
        for (int h = 0; h < 8; ++h) dh[h] = 0.f;
#pragma unroll
        for (int j = 0; j < 16; ++j) {
            int c = j * 32 + l;
            dh[j >> 1] += Cs[wid * 512 + c] * csk[c];
        }
        float wb[8];
#pragma unroll
        for (int h = 0; h < 8; ++h) {
            float A = dh[h];
#pragma unroll
            for (int o = 16; o; o >>= 1) A += __shfl_xor_sync(0xffffffffu, A, o);
            A *= 0.125f;
            float z = (l < cur) ? A * wl : -3.0e38f;
            float mx = z;
#pragma unroll
            for (int o = 16; o; o >>= 1) mx = fmaxf(mx, __shfl_xor_sync(0xffffffffu, mx, o));
            float e = (l < cur) ? expf(z - mx) : 0.f;
            float se = e, sw = e * wl;
#pragma unroll
            for (int o = 16; o; o >>= 1) {
                se += __shfl_xor_sync(0xffffffffu, se, o);
                sw += __shfl_xor_sync(0xffffffffu, sw, o);
            }
            wb[h] = sw / se;
        }
#pragma unroll
        for (int j = 0; j < 16; ++j) {
            int c = j * 32 + l;
            Cs[wid * 512 + c] = wb[j >> 1] * csv[c] + bv[c];
        }
    }
    __syncthreads();
}

// ------------------------------- megakernel --------------------------------
__global__ void __launch_bounds__(NT, 1)
mega(const float* __restrict__ noise, const float* __restrict__ W_in,
     const float* __restrict__ b_in, const float* __restrict__ emb,
     const float* __restrict__ Wsa, const float* __restrict__ bsa,
     const float* __restrict__ Wca, const float* __restrict__ bca,
     const float* __restrict__ Wff, const float* __restrict__ bff,
     const float* __restrict__ ln_g, const float* __restrict__ ln_b,
     const float* __restrict__ soft_W, const float* __restrict__ soft_b,
     float* __restrict__ out)
{
    extern __shared__ float smem[];
    float* Xs = smem;            // 2048
    float* Cs = smem + 2048;     // 2048
    float* Ds = smem + 4096;     // 2048
    float* Ws = smem + 6144;     // 8192 (2 x 8x512)
    int tid = threadIdx.x, bid = blockIdx.x, grid = gridDim.x;
    int gt = bid * NT + tid, gs = grid * NT;

    // =============================== setup ================================
    if (bid == 0) {
        float* s0 = smem; float* s1 = smem + 1024;
        for (int i = tid; i < 1024; i += NT) s0[i] = noise[i];
        __syncthreads();
        for (int m = 0; m < 2; ++m) {
            for (int i = tid; i < 1024; i += NT) {
                int r = i >> 5, c = i & 31;
                float a = b_in[m * 32 + c];
#pragma unroll
                for (int k = 0; k < 32; ++k) a += s0[r*32+k] * W_in[m*1024 + k*32 + c];
                s1[i] = a;
            }
            __syncthreads();
            float* t = s0; s0 = s1; s1 = t;
            __syncthreads();
        }
        for (int i = tid; i < 1024; i += NT) g_W0[i] = s0[i];
    }
    for (int i = gt; i < 16384; i += gs) {
        int s = i >> 9, e = i & 511;
        float div = expf((float)(e & ~1) * (-logf(10000.0f) / 512.0f));
        float ang = (float)s * div;
        g_PE[i] = (e & 1) ? cosf(ang) : sinf(ang);
    }
    for (int i = gt; i < 4096; i += gs) {
        int n2w = i >> 9, j = i & 511;
        int n = n2w >> 1, which = n2w & 1;
        const float* Wp = Wca + (size_t)(n * 4 + 1 + which) * 262144 + j;
        float a = 0.f;
        for (int e = 0; e < 512; ++e) a += Wp[(size_t)e * 512];
        g_GCS[i] = a;
    }
    for (int i = gt; i < 16384; i += gs) {
        int b = i >> 9, e = i & 511;
        g_Y[b * 16384 + e] = emb[e] + ((e & 1) ? 1.f : 0.f);
    }
    for (int i = gt; i < 320000; i += gs) {
        int b = i / 10000, v = i - b * 10000;
        out[(size_t)b * 320000 + v] = (v == 0) ? 1.f : 0.f;
    }
    gsync();

    // ============================ token loop ==============================
    for (int tok = 1; tok < 32; ++tok) {
        int cur = tok, rows = 32 * cur, ntr4 = rows >> 2;
        for (int n = 0; n < 4; ++n) {
            int fromY = (n == 0);
            const float* Xsrc = fromY ? g_Y : g_XB;

            // ---- stage A: K,V GEMMs ----
            for (int u = bid; u < 2 * ntr4; u += grid) {
                int which = u / ntr4, rt = u - which * ntr4, r0 = rt * 4;
                loadX(Xsrc, fromY, cur, r0, Xs);
                float acc[4] = {0.f, 0.f, 0.f, 0.f};
                gemm4(Wsa + (size_t)(n*4 + 1 + which) * 262144, Xs, Ws, acc);
                epi4(acc, bsa + (size_t)(n*4 + 1 + which) * 512,
                     (which ? g_V : g_K) + (size_t)r0 * 512, 0);
            }
            gsync();

            // ---- stage B: fused row-local chain ----
            for (int rt = bid; rt < ntr4; rt += grid) {
                int r0 = rt * 4;
                loadX(Xsrc, fromY, cur, r0, Xs);

                float a1[4] = {0.f,0.f,0.f,0.f};                       // Q
                gemm4(Wsa + (size_t)(n*4+0)*262144, Xs, Ws, a1);
                epi4(a1, bsa + (size_t)(n*4+0)*512, Cs, 0);
                attn4(Cs, Ds, r0, cur);                                 // attn -> Ds

                float a2[4] = {0.f,0.f,0.f,0.f};                       // out-proj
                gemm4(Wsa + (size_t)(n*4+3)*262144, Ds, Ws, a2);
                epi4(a2, bsa + (size_t)(n*4+3)*512, Cs, 0);
                ln4(Cs, Xs, ln_g + (size_t)(n*3)*512, ln_b + (size_t)(n*3)*512, Ds);  // H1 -> Ds

                float a3[4] = {0.f,0.f,0.f,0.f};                       // cross Q
                gemm4(Wca + (size_t)(n*4+0)*262144, Ds, Ws, a3);
                epi4(a3, bca + (size_t)(n*4+0)*512, Cs, 0);
                cross4(Cs, r0, cur, n, bca);                            // collapse in place

                float a4[4] = {0.f,0.f,0.f,0.f};                       // cross out-proj
                gemm4(Wca + (size_t)(n*4+3)*262144, Cs, Ws, a4);
                epi4(a4, bca + (size_t)(n*4+3)*512, Xs, 0);
                ln4(Xs, Ds, ln_g + (size_t)(n*3+1)*512, ln_b + (size_t)(n*3+1)*512, Cs); // H2 -> Cs

                float a5[4] = {0.f,0.f,0.f,0.f};                       // FF1 + relu
                gemm4(Wff + (size_t)(n*2+0)*262144, Cs, Ws, a5);
                epi4(a5, bff + (size_t)(n*2+0)*512, Ds, 1);

                float a6[4] = {0.f,0.f,0.f,0.f};                       // FF2
                gemm4(Wff + (size_t)(n*2+1)*262144, Ds, Ws, a6);
                epi4(a6, bff + (size_t)(n*2+1)*512, Xs, 0);
                ln4(Xs, Cs, ln_g + (size_t)(n*3+2)*512, ln_b + (size_t)(n*3+2)*512,
                    g_XB + (size_t)r0 * 512);
            }
            gsync();
        }

        // ---- logits: xtok(32x512) @ soft_W(512x10000) ----
        for (int tile = bid; tile < 157; tile += grid) {
            __syncthreads();
#pragma unroll
            for (int it = 0; it < 8; ++it) {
                int slot = it * NT + tid;          // 4096 float4 slots (32x512)
                int r = slot >> 7, c4 = slot & 127;
                ((float4*)smem)[slot] =
                    ((const float4*)(g_XB + (size_t)(r * cur + cur - 1) * 512))[c4];
            }
            __syncthreads();
            int ty = tid >> 6, ci = tid & 63;
            int col = tile * 64 + ci;
            int valid = (col < 10000);
            float acc[4] = {0.f, 0.f, 0.f, 0.f};
            for (int k = 0; k < 512; ++k) {
                float wv = valid ? __ldg(soft_W + (size_t)k * 10000 + col) : 0.f;
#pragma unroll
                for (int i = 0; i < 4; ++i)
                    acc[i] += smem[(ty * 4 + i) * 512 + k] * wv;
            }
            if (valid) {
                float sb = soft_b[col];
#pragma unroll
                for (int i = 0; i < 4; ++i)
                    g_LOG[(size_t)(ty * 4 + i) * 10000 + col] = acc[i] + sb;
            }
            __syncthreads();
        }
        gsync();

        // ---- softmax + argmax + next token (CTA per b) ----
        for (int b = bid; b < 32; b += grid) {
            __syncthreads();
            const float* lg = g_LOG + (size_t)b * 10000;
            float* sv = smem;
            int* si = (int*)(smem + NT);
            float mx = -3.0e38f; int mi = 0;
            for (int c = tid; c < 10000; c += NT) {
                float v = lg[c];
                if (v > mx) { mx = v; mi = c; }
            }
            sv[tid] = mx; si[tid] = mi;
            __syncthreads();
            for (int st = NT / 2; st; st >>= 1) {
                if (tid < st) {
                    float v2 = sv[tid + st]; int i2 = si[tid + st];
                    if (v2 > sv[tid] || (v2 == sv[tid] && i2 < si[tid])) {
                        sv[tid] = v2; si[tid] = i2;
                    }
                }
                __syncthreads();
            }
            float gmax = sv[0];
            int id = si[0];
            __syncthreads();
            float s = 0.f;
            for (int c = tid; c < 10000; c += NT) s += expf(lg[c] - gmax);
            sv[tid] = s;
            __syncthreads();
            for (int st = NT / 2; st; st >>= 1) {
                if (tid < st) sv[tid] += sv[tid + st];
                __syncthreads();
            }
            float inv = 1.f / sv[0];
            float* op = out + (size_t)b * 320000 + (size_t)tok * 10000;
            for (int c = tid; c < 10000; c += NT) op[c] = expf(lg[c] - gmax) * inv;
            for (int e = tid; e < 512; e += NT)
                g_Y[b * 16384 + tok * 512 + e] = emb[(size_t)id * 512 + e] + g_PE[tok * 512 + e];
            __syncthreads();
        }
        gsync();
    }
}

// ---------------------------------------------------------------------------
extern "C" void kernel_launch(void* const* d_in, const int* in_sizes, int n_in,
                              void* d_out, int out_size)
{
    const float* noise  = (const float*)d_in[0];
    const float* W_in   = (const float*)d_in[1];
    const float* b_in   = (const float*)d_in[2];
    const float* emb    = (const float*)d_in[3];
    const float* Wsa    = (const float*)d_in[4];
    const float* bsa    = (const float*)d_in[5];
    const float* Wca    = (const float*)d_in[6];
    const float* bca    = (const float*)d_in[7];
    const float* Wff    = (const float*)d_in[8];
    const float* bff    = (const float*)d_in[9];
    const float* ln_g   = (const float*)d_in[10];
    const float* ln_b   = (const float*)d_in[11];
    const float* soft_W = (const float*)d_in[12];
    const float* soft_b = (const float*)d_in[13];
    float* out = (float*)d_out;

    int dev = 0, sms = 148;
    cudaGetDevice(&dev);
    cudaDeviceGetAttribute(&sms, cudaDevAttrMultiProcessorCount, dev);
    if (sms < 32) sms = 32;

    const int smem_bytes = 69632;   // 17408 floats
    cudaFuncSetAttribute(mega, cudaFuncAttributeMaxDynamicSharedMemorySize, smem_bytes);

    mega<<<sms, NT, smem_bytes>>>(noise, W_in, b_in, emb, Wsa, bsa, Wca, bca,
                                  Wff, bff, ln_g, ln_b, soft_W, soft_b, out);
}

// round 7
// speedup vs baseline: 1.4685x; 1.4685x over previous
#include <cuda_runtime.h>
#include <math.h>
#include <stddef.h>

#define RS 507904          /* 992 * 512 */
#define NT 512

__device__ float g_W0[1024];
__device__ float g_PE[16384];
__device__ float g_GCS[4096];
__device__ float g_Y[524288];
__device__ float g_K[RS];
__device__ float g_V[RS];
__device__ float g_XB[RS];
__device__ float g_LOG[320000];
__device__ unsigned g_count;
__device__ volatile unsigned g_sense;

// ------------------------------ grid barrier -------------------------------
__device__ __forceinline__ void gsync()
{
    __threadfence();
    __syncthreads();
    if (threadIdx.x == 0) {
        unsigned gen = g_sense;
        if (atomicAdd(&g_count, 1u) == gridDim.x - 1) {
            g_count = 0;
            __threadfence();
            g_sense = gen + 1;
        } else {
            while (g_sense == gen) __nanosleep(32);
        }
    }
    __syncthreads();
    __threadfence();
}

// ------------------------------ cp.async -----------------------------------
__device__ __forceinline__ void cpa16(float* s, const float* g)
{
    unsigned sa = (unsigned)__cvta_generic_to_shared(s);
    asm volatile("cp.async.cg.shared.global [%0], [%1], 16;\n" :: "r"(sa), "l"(g));
}
#define CPCOMMIT() asm volatile("cp.async.commit_group;\n" ::: "memory")
#define CPWAIT1()  asm volatile("cp.async.wait_group 1;\n" ::: "memory")

// fill one 8x512 weight chunk (4096 floats = 16KB)
__device__ __forceinline__ void fill8(float* buf, const float* gp)
{
    int tid = threadIdx.x;
#pragma unroll
    for (int it = 0; it < 2; ++it) {
        int slot = it * NT + tid;
        cpa16(buf + slot * 4, gp + slot * 4);
    }
}

// ---------------------- templated tile primitives --------------------------
// Tile: R rows x 512 cols. Thread owns column c = tid, all R rows (acc[R]).

template<int R>
__device__ __forceinline__ void loadXT(const float* __restrict__ src, int fromY,
                                       int cur, int r0, float* __restrict__ Xs)
{
    for (int slot = threadIdx.x; slot < R * 128; slot += NT) {
        int row = slot >> 7, c4 = slot & 127;
        int gr = r0 + row;
        const float* rp;
        if (fromY) { int b = gr / cur, s2 = gr - b * cur; rp = src + b * 16384 + s2 * 512; }
        else        rp = src + (size_t)gr * 512;
        ((float4*)Xs)[slot] = ((const float4*)rp)[c4];
    }
    __syncthreads();
}

template<int R>
__device__ __forceinline__ void gemmT(const float* __restrict__ Wp,
                                      const float* __restrict__ As,
                                      float* __restrict__ Ws, float* acc)
{
    int c = threadIdx.x;
    fill8(Ws, Wp); CPCOMMIT();
    for (int ch = 0; ch < 64; ++ch) {
        float* curb = Ws + (ch & 1) * 4096;
        float* nxtb = Ws + ((ch & 1) ^ 1) * 4096;
        if (ch < 63) fill8(nxtb, Wp + (size_t)(ch + 1) * 4096);
        CPCOMMIT();
        CPWAIT1();
        __syncthreads();
#pragma unroll
        for (int half = 0; half < R / 4; ++half) {
            float a[4][8];
#pragma unroll
            for (int r = 0; r < 4; ++r) {
                const float4* ap = (const float4*)(As + (half * 4 + r) * 512 + ch * 8);
                float4 x0 = ap[0], x1 = ap[1];
                a[r][0] = x0.x; a[r][1] = x0.y; a[r][2] = x0.z; a[r][3] = x0.w;
                a[r][4] = x1.x; a[r][5] = x1.y; a[r][6] = x1.z; a[r][7] = x1.w;
            }
#pragma unroll
            for (int kk = 0; kk < 8; ++kk) {
                float w = curb[kk * 512 + c];
#pragma unroll
                for (int r = 0; r < 4; ++r) acc[half * 4 + r] += a[r][kk] * w;
            }
        }
        __syncthreads();
    }
}

template<int R>
__device__ __forceinline__ void epiT(const float* acc, const float* __restrict__ bias,
                                     float* __restrict__ dst, int relu)
{
    int c = threadIdx.x;
    float bb = bias[c];
#pragma unroll
    for (int r = 0; r < R; ++r) {
        float v = acc[r] + bb;
        if (relu) v = fmaxf(v, 0.f);
        dst[r * 512 + c] = v;
    }
    __syncthreads();
}

// LayerNorm of (a + res) -> dst, one warp per row, R warps active
template<int R>
__device__ __forceinline__ void lnT(const float* __restrict__ a, const float* __restrict__ res,
                                    const float* __restrict__ gg, const float* __restrict__ bb,
                                    float* __restrict__ dst)
{
    int wid = threadIdx.x >> 5, l = threadIdx.x & 31;
    if (wid < R) {
        float v[16]; float s = 0.f;
#pragma unroll
        for (int j = 0; j < 16; ++j) {
            int cc = j * 32 + l;
            v[j] = a[wid * 512 + cc] + res[wid * 512 + cc];
            s += v[j];
        }
#pragma unroll
        for (int o = 16; o; o >>= 1) s += __shfl_xor_sync(0xffffffffu, s, o);
        float mean = s * (1.f / 512.f);
        float vs = 0.f;
#pragma unroll
        for (int j = 0; j < 16; ++j) { float d = v[j] - mean; vs += d * d; }
#pragma unroll
        for (int o = 16; o; o >>= 1) vs += __shfl_xor_sync(0xffffffffu, vs, o);
        float inv = rsqrtf(vs * (1.f / 512.f) + 1e-5f);
#pragma unroll
        for (int j = 0; j < 16; ++j) {
            int cc = j * 32 + l;
            dst[wid * 512 + cc] = gg[cc] * (v[j] - mean) * inv + bb[cc];
        }
    }
    __syncthreads();
}

// self-attention: Q rows in Cs -> Ds; K,V in gmem. Lane j owns score_j.
template<int R>
__device__ __forceinline__ void attnT(const float* __restrict__ Cs, float* __restrict__ Ds,
                                      int r0, int cur)
{
    int wid = threadIdx.x >> 5, l = threadIdx.x & 31;
    for (int u = wid; u < R * 8; u += 16) {
        int rl = u >> 3, h = u & 7;
        int gr = r0 + rl, b = gr / cur;
        const float* Kb = g_K + (size_t)(b * cur) * 512 + h * 64;
        const float* Vb = g_V + (size_t)(b * cur) * 512 + h * 64;
        const float* qp = Cs + rl * 512 + h * 64;

        float s = -3.0e38f;
        if (l < cur) {
            const float* Kj = Kb + (size_t)l * 512;
            float dot = 0.f;
#pragma unroll
            for (int d4 = 0; d4 < 16; ++d4) {
                float4 kv = ((const float4*)Kj)[d4];
                float4 qv = ((const float4*)qp)[d4];
                dot += kv.x * qv.x + kv.y * qv.y + kv.z * qv.z + kv.w * qv.w;
            }
            s = dot * 0.125f;
        }
        float mx = s;
#pragma unroll
        for (int o = 16; o; o >>= 1) mx = fmaxf(mx, __shfl_xor_sync(0xffffffffu, mx, o));
        float p = (l < cur) ? expf(s - mx) : 0.f;
        float sum = p;
#pragma unroll
        for (int o = 16; o; o >>= 1) sum += __shfl_xor_sync(0xffffffffu, sum, o);
        p /= sum;

        float a0 = 0.f, a1 = 0.f;
        for (int j = 0; j < cur; ++j) {
            float pj = __shfl_sync(0xffffffffu, p, j);
            a0 += pj * Vb[(size_t)j * 512 + l];
            a1 += pj * Vb[(size_t)j * 512 + l + 32];
        }
        float* dp = Ds + rl * 512 + h * 64;
        dp[l] = a0; dp[l + 32] = a1;
    }
    __syncthreads();
}

// collapsed cross-attention, in place on Cs; warp wid handles row wid
template<int R>
__device__ __forceinline__ void crossT(float* __restrict__ Cs, int r0, int cur,
                                       int n, const float* __restrict__ bca)
{
    int wid = threadIdx.x >> 5, l = threadIdx.x & 31;
    if (wid < R) {
        int gr = r0 + wid, b = gr / cur;
        float wl = (l < cur) ? g_W0[b * 32 + l] : 0.f;
        const float* csk = g_GCS + (n * 2 + 0) * 512;
        const float* csv = g_GCS + (n * 2 + 1) * 512;
        const float* bv  = bca + (size_t)(n * 4 + 2) * 512;
        float dh[8];
#pragma unroll
        for (int h = 0; h < 8; ++h) dh[h] = 0.f;
#pragma unroll
        for (int j = 0; j < 16; ++j) {
            int cc = j * 32 + l;
            dh[j >> 1] += Cs[wid * 512 + cc] * csk[cc];
        }
        float wb[8];
#pragma unroll
        for (int h = 0; h < 8; ++h) {
            float A = dh[h];
#pragma unroll
            for (int o = 16; o; o >>= 1) A += __shfl_xor_sync(0xffffffffu, A, o);
            A *= 0.125f;
            float z = (l < cur) ? A * wl : -3.0e38f;
            float mx = z;
#pragma unroll
            for (int o = 16; o; o >>= 1) mx = fmaxf(mx, __shfl_xor_sync(0xffffffffu, mx, o));
            float e = (l < cur) ? expf(z - mx) : 0.f;
            float se = e, sw = e * wl;
#pragma unroll
            for (int o = 16; o; o >>= 1) {
                se += __shfl_xor_sync(0xffffffffu, se, o);
                sw += __shfl_xor_sync(0xffffffffu, sw, o);
            }
            wb[h] = sw / se;
        }
#pragma unroll
        for (int j = 0; j < 16; ++j) {
            int cc = j * 32 + l;
            Cs[wid * 512 + cc] = wb[j >> 1] * csv[cc] + bv[cc];
        }
    }
    __syncthreads();
}

// ------------------- one transformer block at tile height R ----------------
template<int R>
__device__ void do_block(int n, int cur, int rows, const float* __restrict__ Xsrc, int fromY,
                         const float* __restrict__ Wsa, const float* __restrict__ bsa,
                         const float* __restrict__ Wca, const float* __restrict__ bca,
                         const float* __restrict__ Wff, const float* __restrict__ bff,
                         const float* __restrict__ ln_g, const float* __restrict__ ln_b,
                         float* Xs, float* Cs, float* Ds, float* Ws)
{
    int bid = blockIdx.x, grid = gridDim.x;
    int ntr = rows / R;

    // ---- stage A: K,V GEMMs ----
    for (int u = bid; u < 2 * ntr; u += grid) {
        int which = u / ntr, rt = u - which * ntr, r0 = rt * R;
        loadXT<R>(Xsrc, fromY, cur, r0, Xs);
        float acc[R];
#pragma unroll
        for (int r = 0; r < R; ++r) acc[r] = 0.f;
        gemmT<R>(Wsa + (size_t)(n * 4 + 1 + which) * 262144, Xs, Ws, acc);
        epiT<R>(acc, bsa + (size_t)(n * 4 + 1 + which) * 512,
                (which ? g_V : g_K) + (size_t)r0 * 512, 0);
    }
    gsync();

    // ---- stage B: fused row-local chain ----
    for (int rt = bid; rt < ntr; rt += grid) {
        int r0 = rt * R;
        loadXT<R>(Xsrc, fromY, cur, r0, Xs);
        float acc[R];

#pragma unroll
        for (int r = 0; r < R; ++r) acc[r] = 0.f;               // Q
        gemmT<R>(Wsa + (size_t)(n * 4 + 0) * 262144, Xs, Ws, acc);
        epiT<R>(acc, bsa + (size_t)(n * 4 + 0) * 512, Cs, 0);
        attnT<R>(Cs, Ds, r0, cur);

#pragma unroll
        for (int r = 0; r < R; ++r) acc[r] = 0.f;               // attn out-proj
        gemmT<R>(Wsa + (size_t)(n * 4 + 3) * 262144, Ds, Ws, acc);
        epiT<R>(acc, bsa + (size_t)(n * 4 + 3) * 512, Cs, 0);
        lnT<R>(Cs, Xs, ln_g + (size_t)(n * 3) * 512, ln_b + (size_t)(n * 3) * 512, Ds);

#pragma unroll
        for (int r = 0; r < R; ++r) acc[r] = 0.f;               // cross Q
        gemmT<R>(Wca + (size_t)(n * 4 + 0) * 262144, Ds, Ws, acc);
        epiT<R>(acc, bca + (size_t)(n * 4 + 0) * 512, Cs, 0);
        crossT<R>(Cs, r0, cur, n, bca);

#pragma unroll
        for (int r = 0; r < R; ++r) acc[r] = 0.f;               // cross out-proj
        gemmT<R>(Wca + (size_t)(n * 4 + 3) * 262144, Cs, Ws, acc);
        epiT<R>(acc, bca + (size_t)(n * 4 + 3) * 512, Xs, 0);
        lnT<R>(Xs, Ds, ln_g + (size_t)(n * 3 + 1) * 512, ln_b + (size_t)(n * 3 + 1) * 512, Cs);

#pragma unroll
        for (int r = 0; r < R; ++r) acc[r] = 0.f;               // FF1 + relu
        gemmT<R>(Wff + (size_t)(n * 2 + 0) * 262144, Cs, Ws, acc);
        epiT<R>(acc, bff + (size_t)(n * 2 + 0) * 512, Ds, 1);

#pragma unroll
        for (int r = 0; r < R; ++r) acc[r] = 0.f;               // FF2
        gemmT<R>(Wff + (size_t)(n * 2 + 1) * 262144, Ds, Ws, acc);
        epiT<R>(acc, bff + (size_t)(n * 2 + 1) * 512, Xs, 0);
        lnT<R>(Xs, Cs, ln_g + (size_t)(n * 3 + 2) * 512, ln_b + (size_t)(n * 3 + 2) * 512,
               g_XB + (size_t)r0 * 512);
    }
    gsync();
}

// ------------------------------- megakernel --------------------------------
__global__ void __launch_bounds__(NT, 1)
mega(const float* __restrict__ noise, const float* __restrict__ W_in,
     const float* __restrict__ b_in, const float* __restrict__ emb,
     const float* __restrict__ Wsa, const float* __restrict__ bsa,
     const float* __restrict__ Wca, const float* __restrict__ bca,
     const float* __restrict__ Wff, const float* __restrict__ bff,
     const float* __restrict__ ln_g, const float* __restrict__ ln_b,
     const float* __restrict__ soft_W, const float* __restrict__ soft_b,
     float* __restrict__ out)
{
    extern __shared__ float smem[];
    float* Xs = smem;            // 4096
    float* Cs = smem + 4096;     // 4096
    float* Ds = smem + 8192;     // 4096
    float* Ws = smem + 12288;    // 8192 (2 x 8x512)
    int tid = threadIdx.x, bid = blockIdx.x, grid = gridDim.x;
    int gt = bid * NT + tid, gs = grid * NT;

    // =============================== setup ================================
    if (bid == 0) {
        float* s0 = smem; float* s1 = smem + 1024;
        for (int i = tid; i < 1024; i += NT) s0[i] = noise[i];
        __syncthreads();
        for (int m = 0; m < 2; ++m) {
            for (int i = tid; i < 1024; i += NT) {
                int r = i >> 5, c = i & 31;
                float a = b_in[m * 32 + c];
#pragma unroll
                for (int k = 0; k < 32; ++k) a += s0[r * 32 + k] * W_in[m * 1024 + k * 32 + c];
                s1[i] = a;
            }
            __syncthreads();
            float* t = s0; s0 = s1; s1 = t;
            __syncthreads();
        }
        for (int i = tid; i < 1024; i += NT) g_W0[i] = s0[i];
    }
    for (int i = gt; i < 16384; i += gs) {
        int s = i >> 9, e = i & 511;
        float div = expf((float)(e & ~1) * (-logf(10000.0f) / 512.0f));
        float ang = (float)s * div;
        g_PE[i] = (e & 1) ? cosf(ang) : sinf(ang);
    }
    for (int i = gt; i < 4096; i += gs) {
        int n2w = i >> 9, j = i & 511;
        int n = n2w >> 1, which = n2w & 1;
        const float* Wp = Wca + (size_t)(n * 4 + 1 + which) * 262144 + j;
        float a = 0.f;
        for (int e = 0; e < 512; ++e) a += Wp[(size_t)e * 512];
        g_GCS[i] = a;
    }
    for (int i = gt; i < 16384; i += gs) {
        int b = i >> 9, e = i & 511;
        g_Y[b * 16384 + e] = emb[e] + ((e & 1) ? 1.f : 0.f);
    }
    for (int i = gt; i < 320000; i += gs) {
        int b = i / 10000, v = i - b * 10000;
        out[(size_t)b * 320000 + v] = (v == 0) ? 1.f : 0.f;
    }
    gsync();

    // ============================ token loop ==============================
    for (int tok = 1; tok < 32; ++tok) {
        int cur = tok, rows = 32 * cur;
        for (int n = 0; n < 4; ++n) {
            int fromY = (n == 0);
            const float* Xsrc = fromY ? g_Y : g_XB;
            if (tok <= 18)
                do_block<4>(n, cur, rows, Xsrc, fromY, Wsa, bsa, Wca, bca,
                            Wff, bff, ln_g, ln_b, Xs, Cs, Ds, Ws);
            else
                do_block<8>(n, cur, rows, Xsrc, fromY, Wsa, bsa, Wca, bca,
                            Wff, bff, ln_g, ln_b, Xs, Cs, Ds, Ws);
        }

        // ---- logits: xtok(32x512) @ soft_W(512x10000) ----
        for (int tile = bid; tile < 157; tile += grid) {
            __syncthreads();
#pragma unroll
            for (int it = 0; it < 8; ++it) {
                int slot = it * NT + tid;          // 4096 float4 slots (32x512)
                int r = slot >> 7, c4 = slot & 127;
                ((float4*)smem)[slot] =
                    ((const float4*)(g_XB + (size_t)(r * cur + cur - 1) * 512))[c4];
            }
            __syncthreads();
            int ty = tid >> 6, ci = tid & 63;
            int col = tile * 64 + ci;
            int valid = (col < 10000);
            float acc[4] = {0.f, 0.f, 0.f, 0.f};
#pragma unroll 8
            for (int k = 0; k < 512; ++k) {
                float wv = valid ? __ldg(soft_W + (size_t)k * 10000 + col) : 0.f;
#pragma unroll
                for (int i = 0; i < 4; ++i)
                    acc[i] += smem[(ty * 4 + i) * 512 + k] * wv;
            }
            if (valid) {
                float sb = soft_b[col];
#pragma unroll
                for (int i = 0; i < 4; ++i)
                    g_LOG[(size_t)(ty * 4 + i) * 10000 + col] = acc[i] + sb;
            }
            __syncthreads();
        }
        gsync();

        // ---- softmax + argmax + next token (CTA per b) ----
        for (int b = bid; b < 32; b += grid) {
            __syncthreads();
            const float* lg = g_LOG + (size_t)b * 10000;
            float* sv = smem;
            int* si = (int*)(smem + NT);
            float mx = -3.0e38f; int mi = 0;
            for (int c = tid; c < 10000; c += NT) {
                float v = lg[c];
                if (v > mx) { mx = v; mi = c; }
            }
            sv[tid] = mx; si[tid] = mi;
            __syncthreads();
            for (int st = NT / 2; st; st >>= 1) {
                if (tid < st) {
                    float v2 = sv[tid + st]; int i2 = si[tid + st];
                    if (v2 > sv[tid] || (v2 == sv[tid] && i2 < si[tid])) {
                        sv[tid] = v2; si[tid] = i2;
                    }
                }
                __syncthreads();
            }
            float gmax = sv[0];
            int id = si[0];
            __syncthreads();
            float s = 0.f;
            for (int c = tid; c < 10000; c += NT) s += expf(lg[c] - gmax);
            sv[tid] = s;
            __syncthreads();
            for (int st = NT / 2; st; st >>= 1) {
                if (tid < st) sv[tid] += sv[tid + st];
                __syncthreads();
            }
            float inv = 1.f / sv[0];
            float* op = out + (size_t)b * 320000 + (size_t)tok * 10000;
            for (int c = tid; c < 10000; c += NT) op[c] = expf(lg[c] - gmax) * inv;
            for (int e = tid; e < 512; e += NT)
                g_Y[b * 16384 + tok * 512 + e] = emb[(size_t)id * 512 + e] + g_PE[tok * 512 + e];
            __syncthreads();
        }
        gsync();
    }
}

// ---------------------------------------------------------------------------
extern "C" void kernel_launch(void* const* d_in, const int* in_sizes, int n_in,
                              void* d_out, int out_size)
{
    const float* noise  = (const float*)d_in[0];
    const float* W_in   = (const float*)d_in[1];
    const float* b_in   = (const float*)d_in[2];
    const float* emb    = (const float*)d_in[3];
    const float* Wsa    = (const float*)d_in[4];
    const float* bsa    = (const float*)d_in[5];
    const float* Wca    = (const float*)d_in[6];
    const float* bca    = (const float*)d_in[7];
    const float* Wff    = (const float*)d_in[8];
    const float* bff    = (const float*)d_in[9];
    const float* ln_g   = (const float*)d_in[10];
    const float* ln_b   = (const float*)d_in[11];
    const float* soft_W = (const float*)d_in[12];
    const float* soft_b = (const float*)d_in[13];
    float* out = (float*)d_out;

    int dev = 0, sms = 148;
    cudaGetDevice(&dev);
    cudaDeviceGetAttribute(&sms, cudaDevAttrMultiProcessorCount, dev);
    if (sms < 32) sms = 32;

    const int smem_bytes = 81920;   // 20480 floats: Xs|Cs|Ds|Ws
    cudaFuncSetAttribute(mega, cudaFuncAttributeMaxDynamicSharedMemorySize, smem_bytes);

    mega<<<sms, NT, smem_bytes>>>(noise, W_in, b_in, emb, Wsa, bsa, Wca, bca,
                                  Wff, bff, ln_g, ln_b, soft_W, soft_b, out);
}

// round 10
// speedup vs baseline: 2.0473x; 1.3941x over previous
#include <cuda_runtime.h>
#include <math.h>
#include <stddef.h>

#define RS 507904          /* 992 * 512 */
#define NT 512

__device__ float g_W0[1024];
__device__ float g_PE[16384];
__device__ float g_GCS[4096];
__device__ float g_T[16384];       // [n][c][h] 4*512*8
__device__ float g_S0[32];         // [n][h]
__device__ float g_U[16384];       // [n][h][c]
__device__ float g_V0[2048];       // [n][c]
__device__ float g_Y[524288];
__device__ float g_Q[RS];
__device__ float g_K[RS];
__device__ float g_V[RS];
__device__ float g_XB[RS];
__device__ float g_LOG[320000];
__device__ unsigned g_count;
__device__ volatile unsigned g_sense;

// ------------------------------ grid barrier -------------------------------
__device__ __forceinline__ void gsync()
{
    __threadfence();
    __syncthreads();
    if (threadIdx.x == 0) {
        unsigned gen = g_sense;
        if (atomicAdd(&g_count, 1u) == gridDim.x - 1) {
            g_count = 0;
            __threadfence();
            g_sense = gen + 1;
        } else {
            while (g_sense == gen) __nanosleep(32);
        }
    }
    __syncthreads();
    __threadfence();
}

// ------------------------------ cp.async -----------------------------------
__device__ __forceinline__ void cpa16(float* s, const float* g)
{
    unsigned sa = (unsigned)__cvta_generic_to_shared(s);
    asm volatile("cp.async.cg.shared.global [%0], [%1], 16;\n" :: "r"(sa), "l"(g));
}
#define CPCOMMIT() asm volatile("cp.async.commit_group;\n" ::: "memory")
#define CPWAIT1()  asm volatile("cp.async.wait_group 1;\n" ::: "memory")

__device__ __forceinline__ void fill8(float* buf, const float* gp)
{
    int tid = threadIdx.x;
#pragma unroll
    for (int it = 0; it < 2; ++it) {
        int slot = it * NT + tid;
        cpa16(buf + slot * 4, gp + slot * 4);
    }
}

// ---------------------- templated tile primitives --------------------------
template<int R>
__device__ __forceinline__ void loadXT(const float* __restrict__ src, int fromY,
                                       int cur, int r0, float* __restrict__ Xs)
{
    for (int slot = threadIdx.x; slot < R * 128; slot += NT) {
        int row = slot >> 7, c4 = slot & 127;
        int gr = r0 + row;
        const float* rp;
        if (fromY) { int b = gr / cur, s2 = gr - b * cur; rp = src + b * 16384 + s2 * 512; }
        else        rp = src + (size_t)gr * 512;
        ((float4*)Xs)[slot] = ((const float4*)rp)[c4];
    }
    __syncthreads();
}

template<int R>
__device__ __forceinline__ void gemmT(const float* __restrict__ Wp,
                                      const float* __restrict__ As,
                                      float* __restrict__ Ws, float* acc)
{
    int c = threadIdx.x;
    fill8(Ws, Wp); CPCOMMIT();
    for (int ch = 0; ch < 64; ++ch) {
        float* curb = Ws + (ch & 1) * 4096;
        float* nxtb = Ws + ((ch & 1) ^ 1) * 4096;
        if (ch < 63) fill8(nxtb, Wp + (size_t)(ch + 1) * 4096);
        CPCOMMIT();
        CPWAIT1();
        __syncthreads();
#pragma unroll
        for (int half = 0; half < R / 4; ++half) {
            float a[4][8];
#pragma unroll
            for (int r = 0; r < 4; ++r) {
                const float4* ap = (const float4*)(As + (half * 4 + r) * 512 + ch * 8);
                float4 x0 = ap[0], x1 = ap[1];
                a[r][0] = x0.x; a[r][1] = x0.y; a[r][2] = x0.z; a[r][3] = x0.w;
                a[r][4] = x1.x; a[r][5] = x1.y; a[r][6] = x1.z; a[r][7] = x1.w;
            }
#pragma unroll
            for (int kk = 0; kk < 8; ++kk) {
                float w = curb[kk * 512 + c];
#pragma unroll
                for (int r = 0; r < 4; ++r) acc[half * 4 + r] += a[r][kk] * w;
            }
        }
        __syncthreads();
    }
}

template<int R>
__device__ __forceinline__ void epiT(const float* acc, const float* __restrict__ bias,
                                     float* __restrict__ dst, int relu)
{
    int c = threadIdx.x;
    float bb = bias[c];
#pragma unroll
    for (int r = 0; r < R; ++r) {
        float v = acc[r] + bb;
        if (relu) v = fmaxf(v, 0.f);
        dst[r * 512 + c] = v;
    }
    __syncthreads();
}

template<int R>
__device__ __forceinline__ void lnT(const float* __restrict__ a, const float* __restrict__ res,
                                    const float* __restrict__ gg, const float* __restrict__ bb,
                                    float* __restrict__ dst)
{
    int wid = threadIdx.x >> 5, l = threadIdx.x & 31;
    if (wid < R) {
        float v[16]; float s = 0.f;
#pragma unroll
        for (int j = 0; j < 16; ++j) {
            int cc = j * 32 + l;
            v[j] = a[wid * 512 + cc] + res[wid * 512 + cc];
            s += v[j];
        }
#pragma unroll
        for (int o = 16; o; o >>= 1) s += __shfl_xor_sync(0xffffffffu, s, o);
        float mean = s * (1.f / 512.f);
        float vs = 0.f;
#pragma unroll
        for (int j = 0; j < 16; ++j) { float d = v[j] - mean; vs += d * d; }
#pragma unroll
        for (int o = 16; o; o >>= 1) vs += __shfl_xor_sync(0xffffffffu, vs, o);
        float inv = rsqrtf(vs * (1.f / 512.f) + 1e-5f);
#pragma unroll
        for (int j = 0; j < 16; ++j) {
            int cc = j * 32 + l;
            dst[wid * 512 + cc] = gg[cc] * (v[j] - mean) * inv + bb[cc];
        }
    }
    __syncthreads();
}

// self-attention: Q/K/V in gmem -> Ds. Lane j owns score_j.
template<int R>
__device__ __forceinline__ void attnG(float* __restrict__ Ds, int r0, int cur)
{
    int wid = threadIdx.x >> 5, l = threadIdx.x & 31;
    for (int u = wid; u < R * 8; u += 16) {
        int rl = u >> 3, h = u & 7;
        int gr = r0 + rl, b = gr / cur;
        const float* Kb = g_K + (size_t)(b * cur) * 512 + h * 64;
        const float* Vb = g_V + (size_t)(b * cur) * 512 + h * 64;
        const float* qp = g_Q + (size_t)gr * 512 + h * 64;

        float s = -3.0e38f;
        if (l < cur) {
            const float* Kj = Kb + (size_t)l * 512;
            float dot = 0.f;
#pragma unroll
            for (int d4 = 0; d4 < 16; ++d4) {
                float4 kv = ((const float4*)Kj)[d4];
                float4 qv = ((const float4*)qp)[d4];
                dot += kv.x * qv.x + kv.y * qv.y + kv.z * qv.z + kv.w * qv.w;
            }
            s = dot * 0.125f;
        }
        float mx = s;
#pragma unroll
        for (int o = 16; o; o >>= 1) mx = fmaxf(mx, __shfl_xor_sync(0xffffffffu, mx, o));
        float p = (l < cur) ? expf(s - mx) : 0.f;
        float sum = p;
#pragma unroll
        for (int o = 16; o; o >>= 1) sum += __shfl_xor_sync(0xffffffffu, sum, o);
        p /= sum;

        float a0 = 0.f, a1 = 0.f;
        for (int j = 0; j < cur; ++j) {
            float pj = __shfl_sync(0xffffffffu, p, j);
            a0 += pj * Vb[(size_t)j * 512 + l];
            a1 += pj * Vb[(size_t)j * 512 + l + 32];
        }
        float* dp = Ds + rl * 512 + h * 64;
        dp[l] = a0; dp[l + 32] = a1;
    }
    __syncthreads();
}

// collapsed cross-attention: H1 (smem, R rows) -> Co (smem). Whole sub-layer.
template<int R>
__device__ __forceinline__ void crossTiny(const float* __restrict__ H1,
                                          float* __restrict__ Co,
                                          int r0, int cur, int n, float* s_wbar)
{
    int wid = threadIdx.x >> 5, l = threadIdx.x & 31;
    if (wid < R) {
        int gr = r0 + wid, b = gr / cur;
        const float* Trow = g_T + (size_t)n * 4096;
        float A[8];
#pragma unroll
        for (int h = 0; h < 8; ++h) A[h] = 0.f;
#pragma unroll
        for (int k = 0; k < 16; ++k) {
            int c = k * 32 + l;
            float hv = H1[wid * 512 + c];
            const float4* tp = (const float4*)(Trow + c * 8);
            float4 t0 = tp[0], t1 = tp[1];
            A[0] += hv * t0.x; A[1] += hv * t0.y; A[2] += hv * t0.z; A[3] += hv * t0.w;
            A[4] += hv * t1.x; A[5] += hv * t1.y; A[6] += hv * t1.z; A[7] += hv * t1.w;
        }
        float wl = (l < cur) ? g_W0[b * 32 + l] : 0.f;
        float wb[8];
#pragma unroll
        for (int h = 0; h < 8; ++h) {
            float Ah = A[h];
#pragma unroll
            for (int o = 16; o; o >>= 1) Ah += __shfl_xor_sync(0xffffffffu, Ah, o);
            Ah = (Ah + g_S0[n * 8 + h]) * 0.125f;
            float z = (l < cur) ? Ah * wl : -3.0e38f;
            float mx = z;
#pragma unroll
            for (int o = 16; o; o >>= 1) mx = fmaxf(mx, __shfl_xor_sync(0xffffffffu, mx, o));
            float e = (l < cur) ? expf(z - mx) : 0.f;
            float se = e, sw = e * wl;
#pragma unroll
            for (int o = 16; o; o >>= 1) {
                se += __shfl_xor_sync(0xffffffffu, se, o);
                sw += __shfl_xor_sync(0xffffffffu, sw, o);
            }
            wb[h] = sw / se;
        }
        if (l == 0) {
#pragma unroll
            for (int h = 0; h < 8; ++h) s_wbar[wid * 8 + h] = wb[h];
        }
    }
    __syncthreads();
    int c = threadIdx.x;
    const float* Un = g_U + (size_t)n * 4096;
    float u[8];
#pragma unroll
    for (int h = 0; h < 8; ++h) u[h] = Un[h * 512 + c];
    float v0 = g_V0[n * 512 + c];
#pragma unroll
    for (int r = 0; r < R; ++r) {
        float o = v0;
#pragma unroll
        for (int h = 0; h < 8; ++h) o += s_wbar[r * 8 + h] * u[h];
        Co[r * 512 + c] = o;
    }
    __syncthreads();
}

// ------------------- one transformer block at tile height R ----------------
template<int R>
__device__ void do_block(int n, int cur, int rows, const float* __restrict__ Xsrc, int fromY,
                         const float* __restrict__ Wsa, const float* __restrict__ bsa,
                         const float* __restrict__ Wff, const float* __restrict__ bff,
                         const float* __restrict__ ln_g, const float* __restrict__ ln_b,
                         float* Xs, float* Cs, float* Ds, float* Ws, float* s_wbar)
{
    int bid = blockIdx.x, grid = gridDim.x;
    int ntr = rows / R;

    // ---- stage A: Q,K,V GEMMs (parallel tiles) ----
    for (int u = bid; u < 3 * ntr; u += grid) {
        int which = u / ntr, rt = u - which * ntr, r0 = rt * R;
        loadXT<R>(Xsrc, fromY, cur, r0, Xs);
        float acc[R];
#pragma unroll
        for (int r = 0; r < R; ++r) acc[r] = 0.f;
        gemmT<R>(Wsa + (size_t)(n * 4 + which) * 262144, Xs, Ws, acc);
        float* dst = (which == 0 ? g_Q : (which == 1 ? g_K : g_V)) + (size_t)r0 * 512;
        epiT<R>(acc, bsa + (size_t)(n * 4 + which) * 512, dst, 0);
    }
    gsync();

    // ---- stage B: fused row-local chain (attn -> O -> cross -> FF) ----
    for (int rt = bid; rt < ntr; rt += grid) {
        int r0 = rt * R;
        loadXT<R>(Xsrc, fromY, cur, r0, Xs);
        float acc[R];

        attnG<R>(Ds, r0, cur);                                   // attn -> Ds

#pragma unroll
        for (int r = 0; r < R; ++r) acc[r] = 0.f;                // O-proj
        gemmT<R>(Wsa + (size_t)(n * 4 + 3) * 262144, Ds, Ws, acc);
        epiT<R>(acc, bsa + (size_t)(n * 4 + 3) * 512, Cs, 0);
        lnT<R>(Cs, Xs, ln_g + (size_t)(n * 3) * 512, ln_b + (size_t)(n * 3) * 512, Ds);

        crossTiny<R>(Ds, Cs, r0, cur, n, s_wbar);                // cross -> Cs
        lnT<R>(Cs, Ds, ln_g + (size_t)(n * 3 + 1) * 512, ln_b + (size_t)(n * 3 + 1) * 512, Xs);

#pragma unroll
        for (int r = 0; r < R; ++r) acc[r] = 0.f;                // FF1 + relu
        gemmT<R>(Wff + (size_t)(n * 2 + 0) * 262144, Xs, Ws, acc);
        epiT<R>(acc, bff + (size_t)(n * 2 + 0) * 512, Cs, 1);

#pragma unroll
        for (int r = 0; r < R; ++r) acc[r] = 0.f;                // FF2
        gemmT<R>(Wff + (size_t)(n * 2 + 1) * 262144, Cs, Ws, acc);
        epiT<R>(acc, bff + (size_t)(n * 2 + 1) * 512, Ds, 0);
        lnT<R>(Ds, Xs, ln_g + (size_t)(n * 3 + 2) * 512, ln_b + (size_t)(n * 3 + 2) * 512,
               g_XB + (size_t)r0 * 512);
    }
    gsync();
}

// ------------------------------- megakernel --------------------------------
__global__ void __launch_bounds__(NT, 1)
mega(const float* __restrict__ noise, const float* __restrict__ W_in,
     const float* __restrict__ b_in, const float* __restrict__ emb,
     const float* __restrict__ Wsa, const float* __restrict__ bsa,
     const float* __restrict__ Wca, const float* __restrict__ bca,
     const float* __restrict__ Wff, const float* __restrict__ bff,
     const float* __restrict__ ln_g, const float* __restrict__ ln_b,
     const float* __restrict__ soft_W, const float* __restrict__ soft_b,
     float* __restrict__ out)
{
    extern __shared__ float smem[];
    float* Xs = smem;            // 4096
    float* Cs = smem + 4096;     // 4096
    float* Ds = smem + 8192;     // 4096
    float* Ws = smem + 12288;    // 8192
    __shared__ float s_wbar[64];
    int tid = threadIdx.x, bid = blockIdx.x, grid = gridDim.x;
    int gt = bid * NT + tid, gs = grid * NT;

    // ============================ setup phase 0 ===========================
    if (bid == 0) {
        float* s0 = smem; float* s1 = smem + 1024;
        for (int i = tid; i < 1024; i += NT) s0[i] = noise[i];
        __syncthreads();
        for (int m = 0; m < 2; ++m) {
            for (int i = tid; i < 1024; i += NT) {
                int r = i >> 5, c = i & 31;
                float a = b_in[m * 32 + c];
#pragma unroll
                for (int k = 0; k < 32; ++k) a += s0[r * 32 + k] * W_in[m * 1024 + k * 32 + c];
                s1[i] = a;
            }
            __syncthreads();
            float* t = s0; s0 = s1; s1 = t;
            __syncthreads();
        }
        for (int i = tid; i < 1024; i += NT) g_W0[i] = s0[i];
    }
    for (int i = gt; i < 16384; i += gs) {
        int s = i >> 9, e = i & 511;
        float div = expf((float)(e & ~1) * (-logf(10000.0f) / 512.0f));
        float ang = (float)s * div;
        g_PE[i] = (e & 1) ? cosf(ang) : sinf(ang);
    }
    for (int i = gt; i < 4096; i += gs) {               // colsums of Wca k/v
        int n2w = i >> 9, j = i & 511;
        int n = n2w >> 1, which = n2w & 1;
        const float* Wp = Wca + (size_t)(n * 4 + 1 + which) * 262144 + j;
        float a = 0.f;
        for (int e = 0; e < 512; ++e) a += Wp[(size_t)e * 512];
        g_GCS[i] = a;
    }
    for (int i = gt; i < 16384; i += gs) {
        int b = i >> 9, e = i & 511;
        g_Y[b * 16384 + e] = emb[e] + ((e & 1) ? 1.f : 0.f);
    }
    for (int i = gt; i < 320000; i += gs) {
        int b = i / 10000, v = i - b * 10000;
        out[(size_t)b * 320000 + v] = (v == 0) ? 1.f : 0.f;
    }
    gsync();

    // ============================ setup phase 1 ===========================
    // T[n][c][h] = sum_{j in head h} Wq[c][j]*csk[j]   (warp per (n,c))
    {
        int gw = bid * 16 + (tid >> 5);
        int l = tid & 31;
        if (gw < 2048) {
            int n = gw >> 9, c = gw & 511;
            const float* Wq = Wca + (size_t)(n * 4 + 0) * 262144 + (size_t)c * 512;
            const float* csk = g_GCS + (n * 2 + 0) * 512;
            float A[8];
#pragma unroll
            for (int h = 0; h < 8; ++h) A[h] = 0.f;
#pragma unroll
            for (int k = 0; k < 16; ++k) {
                int j = k * 32 + l;
                A[k >> 1] += Wq[j] * csk[j];
            }
#pragma unroll
            for (int h = 0; h < 8; ++h) {
                float s = A[h];
#pragma unroll
                for (int o = 16; o; o >>= 1) s += __shfl_xor_sync(0xffffffffu, s, o);
                A[h] = s;
            }
            if (l == 0) {
#pragma unroll
                for (int h = 0; h < 8; ++h)
                    g_T[((size_t)n * 512 + c) * 8 + h] = A[h];
            }
        }
    }
    // s0[n][h] = sum_{j in h} bq[j]*csk[j]   (thread per (n,h))
    if (gt < 32) {
        int n = gt >> 3, h = gt & 7;
        const float* bq = bca + (size_t)(n * 4 + 0) * 512;
        const float* csk = g_GCS + (n * 2 + 0) * 512;
        float a = 0.f;
        for (int d = 0; d < 64; ++d) { int j = h * 64 + d; a += bq[j] * csk[j]; }
        g_S0[gt] = a;
    }
    // U[n][h][c], V0[n][c]   (thread per (n,c), coalesced over c)
    if (gt < 2048) {
        int n = gt >> 9, c = gt & 511;
        const float* Wo = Wca + (size_t)(n * 4 + 3) * 262144;
        const float* csv = g_GCS + (n * 2 + 1) * 512;
        const float* bv  = bca + (size_t)(n * 4 + 2) * 512;
        float accv = 0.f;
#pragma unroll
        for (int h = 0; h < 8; ++h) {
            float acc = 0.f;
            for (int d = 0; d < 64; ++d) {
                int j = h * 64 + d;
                float wo = Wo[(size_t)j * 512 + c];
                acc  += csv[j] * wo;
                accv += bv[j] * wo;
            }
            g_U[((size_t)n * 8 + h) * 512 + c] = acc;
        }
        g_V0[(size_t)n * 512 + c] = accv + bca[(size_t)(n * 4 + 3) * 512 + c];
    }
    gsync();

    // ============================ token loop ==============================
    for (int tok = 1; tok < 32; ++tok) {
        int cur = tok, rows = 32 * cur;
        for (int n = 0; n < 4; ++n) {
            int fromY = (n == 0);
            const float* Xsrc = fromY ? g_Y : g_XB;
            if (tok <= 18)
                do_block<4>(n, cur, rows, Xsrc, fromY, Wsa, bsa,
                            Wff, bff, ln_g, ln_b, Xs, Cs, Ds, Ws, s_wbar);
            else
                do_block<8>(n, cur, rows, Xsrc, fromY, Wsa, bsa,
                            Wff, bff, ln_g, ln_b, Xs, Cs, Ds, Ws, s_wbar);
        }

        // ---- logits: xtok(32x512) @ soft_W(512x10000) ----
        for (int tile = bid; tile < 157; tile += grid) {
            __syncthreads();
#pragma unroll
            for (int it = 0; it < 8; ++it) {
                int slot = it * NT + tid;
                int r = slot >> 7, c4 = slot & 127;
                ((float4*)smem)[slot] =
                    ((const float4*)(g_XB + (size_t)(r * cur + cur - 1) * 512))[c4];
            }
            __syncthreads();
            int ty = tid >> 6, ci = tid & 63;
            int col = tile * 64 + ci;
            int valid = (col < 10000);
            float acc[4] = {0.f, 0.f, 0.f, 0.f};
#pragma unroll 8
            for (int k = 0; k < 512; ++k) {
                float wv = valid ? __ldg(soft_W + (size_t)k * 10000 + col) : 0.f;
#pragma unroll
                for (int i = 0; i < 4; ++i)
                    acc[i] += smem[(ty * 4 + i) * 512 + k] * wv;
            }
            if (valid) {
                float sb = soft_b[col];
#pragma unroll
                for (int i = 0; i < 4; ++i)
                    g_LOG[(size_t)(ty * 4 + i) * 10000 + col] = acc[i] + sb;
            }
            __syncthreads();
        }
        gsync();

        // ---- softmax + argmax + next token (CTA per b) ----
        for (int b = bid; b < 32; b += grid) {
            __syncthreads();
            const float* lg = g_LOG + (size_t)b * 10000;
            float* sv = smem;
            int* si = (int*)(smem + NT);
            float mx = -3.0e38f; int mi = 0;
            for (int c = tid; c < 10000; c += NT) {
                float v = lg[c];
                if (v > mx) { mx = v; mi = c; }
            }
            sv[tid] = mx; si[tid] = mi;
            __syncthreads();
            for (int st = NT / 2; st; st >>= 1) {
                if (tid < st) {
                    float v2 = sv[tid + st]; int i2 = si[tid + st];
                    if (v2 > sv[tid] || (v2 == sv[tid] && i2 < si[tid])) {
                        sv[tid] = v2; si[tid] = i2;
                    }
                }
                __syncthreads();
            }
            float gmax = sv[0];
            int id = si[0];
            __syncthreads();
            float s = 0.f;
            for (int c = tid; c < 10000; c += NT) s += expf(lg[c] - gmax);
            sv[tid] = s;
            __syncthreads();
            for (int st = NT / 2; st; st >>= 1) {
                if (tid < st) sv[tid] += sv[tid + st];
                __syncthreads();
            }
            float inv = 1.f / sv[0];
            float* op = out + (size_t)b * 320000 + (size_t)tok * 10000;
            for (int c = tid; c < 10000; c += NT) op[c] = expf(lg[c] - gmax) * inv;
            for (int e = tid; e < 512; e += NT)
                g_Y[b * 16384 + tok * 512 + e] = emb[(size_t)id * 512 + e] + g_PE[tok * 512 + e];
            __syncthreads();
        }
        gsync();
    }
}

// ---------------------------------------------------------------------------
extern "C" void kernel_launch(void* const* d_in, const int* in_sizes, int n_in,
                              void* d_out, int out_size)
{
    const float* noise  = (const float*)d_in[0];
    const float* W_in   = (const float*)d_in[1];
    const float* b_in   = (const float*)d_in[2];
    const float* emb    = (const float*)d_in[3];
    const float* Wsa    = (const float*)d_in[4];
    const float* bsa    = (const float*)d_in[5];
    const float* Wca    = (const float*)d_in[6];
    const float* bca    = (const float*)d_in[7];
    const float* Wff    = (const float*)d_in[8];
    const float* bff    = (const float*)d_in[9];
    const float* ln_g   = (const float*)d_in[10];
    const float* ln_b   = (const float*)d_in[11];
    const float* soft_W = (const float*)d_in[12];
    const float* soft_b = (const float*)d_in[13];
    float* out = (float*)d_out;

    int dev = 0, sms = 148;
    cudaGetDevice(&dev);
    cudaDeviceGetAttribute(&sms, cudaDevAttrMultiProcessorCount, dev);
    if (sms < 32) sms = 32;
    if (sms > 148) sms = 148;   // barrier requires all CTAs co-resident

    const int smem_bytes = 81920;
    cudaFuncSetAttribute(mega, cudaFuncAttributeMaxDynamicSharedMemorySize, smem_bytes);

    mega<<<sms, NT, smem_bytes>>>(noise, W_in, b_in, emb, Wsa, bsa, Wca, bca,
                                  Wff, bff, ln_g, ln_b, soft_W, soft_b, out);
}